// round 3
// baseline (speedup 1.0000x reference)
#include <cuda_runtime.h>

// Problem constants
#define BB 8
#define SS 2048
#define HH 8192
#define RR 16

// Tiling
#define TILE_S 32            // s-rows per block
#define NW 4                 // warps per block == H-windows
#define CH 128               // h chunk per window per iteration
#define HQ (HH / NW)         // 2048 h per window
#define NC (HQ / CH)         // 16 chunks
#define XPAD 4
#define XSTR (CH + XPAD)     // 132 floats: stride%32==4 -> conflict-free LDS.128

#define SMEM_FLOATS (NW * TILE_S * XSTR + NW * RR * CH)   // 16896 + 8192 = 25088
#define SMEM_BYTES  (SMEM_FLOATS * 4)                      // 100352 B

__device__ __forceinline__ void fma2(unsigned long long& acc,
                                     unsigned long long a,
                                     unsigned long long b) {
    asm("fma.rn.f32x2 %0, %1, %2, %0;" : "+l"(acc) : "l"(a), "l"(b));
}

__global__ __launch_bounds__(128, 2)
void lora_bsr_kernel(const float* __restrict__ x,
                     const float* __restrict__ w,
                     const int* __restrict__ ids,
                     float* __restrict__ out)
{
    extern __shared__ float sm[];
    float* xsm = sm;                             // [NW][TILE_S][XSTR]
    float* wsm = sm + NW * TILE_S * XSTR;        // [NW][RR][CH]

    const int tile = blockIdx.x;                 // 0..511
    const int b  = tile >> 6;                    // 64 tiles per batch
    const int s0 = (tile & 63) * TILE_S;
    const int aid = ids[b];

    const float* __restrict__ xb = x + (size_t)(b * SS + s0) * HH;
    const float* __restrict__ wb = w + (size_t)aid * RR * HH;

    const int tid  = threadIdx.x;
    const int warp = tid >> 5;
    const int lane = tid & 31;

    unsigned long long acc[RR];
#pragma unroll
    for (int r = 0; r < RR; r++) acc[r] = 0ULL;

    for (int ci = 0; ci < NC; ci++) {
        const int hoff = ci * CH;

        // ---- stage x tile: NW*TILE_S*CH floats = 4096 float4, coalesced ----
#pragma unroll
        for (int i = 0; i < 32; i++) {
            const int idx = tid + i * 128;           // 0..4095
            const int v   = idx & 31;                // float4 within row
            const int row = (idx >> 5) & 31;
            const int wnd = idx >> 10;
            const float4 g = *(const float4*)(xb + (size_t)row * HH
                                              + wnd * HQ + hoff + v * 4);
            *(float4*)(xsm + (wnd * TILE_S + row) * XSTR + v * 4) = g;
        }
        // ---- stage w tile: NW*RR*CH floats = 2048 float4, coalesced ----
#pragma unroll
        for (int i = 0; i < 16; i++) {
            const int idx = tid + i * 128;           // 0..2047
            const int v   = idx & 31;
            const int r   = (idx >> 5) & 15;
            const int wnd = idx >> 9;
            const float4 g = *(const float4*)(wb + (size_t)r * HH
                                              + wnd * HQ + hoff + v * 4);
            *(float4*)(wsm + (wnd * RR + r) * CH + v * 4) = g;
        }
        __syncthreads();

        // ---- compute: lane == row, warp == h-window; weight reads broadcast ----
        const float* xrow = xsm + (warp * TILE_S + lane) * XSTR;
        const float* wwin = wsm + warp * RR * CH;
#pragma unroll 4
        for (int hh = 0; hh < CH; hh += 4) {
            const ulonglong2 xv = *(const ulonglong2*)(xrow + hh);
#pragma unroll
            for (int r = 0; r < RR; r++) {
                const ulonglong2 wv = *(const ulonglong2*)(wwin + r * CH + hh);
                fma2(acc[r], xv.x, wv.x);
                fma2(acc[r], xv.y, wv.y);
            }
        }
        __syncthreads();
    }

    // ---- cross-window reduction (reuse smem; all warps past final barrier) ----
    float* red = sm;                                 // [NW][TILE_S][RR+1]
#pragma unroll
    for (int r = 0; r < RR; r++) {
        union { unsigned long long u; float2 f; } cv;
        cv.u = acc[r];
        red[(warp * TILE_S + lane) * (RR + 1) + r] = cv.f.x + cv.f.y;
    }
    __syncthreads();

#pragma unroll
    for (int i = 0; i < 4; i++) {
        const int o   = tid + i * 128;               // 0..511
        const int r   = o & 15;
        const int row = o >> 4;
        float s = 0.f;
#pragma unroll
        for (int wd = 0; wd < NW; wd++)
            s += red[(wd * TILE_S + row) * (RR + 1) + r];
        out[((size_t)(b * SS) + s0 + row) * RR + r] = s;
    }
}

extern "C" void kernel_launch(void* const* d_in, const int* in_sizes, int n_in,
                              void* d_out, int out_size) {
    const float* x   = (const float*)d_in[0];   // [B, S, H] f32
    const float* w   = (const float*)d_in[1];   // [MAX_LORAS, R, H] f32
    // d_in[2] = weight_active: dead input (reference overwrites all B slots)
    const int*   ids = (const int*)d_in[3];     // [B] i32
    float* out = (float*)d_out;                 // [B, S, R] f32

    cudaFuncSetAttribute(lora_bsr_kernel,
                         cudaFuncAttributeMaxDynamicSharedMemorySize, SMEM_BYTES);

    const int tiles = BB * (SS / TILE_S);       // 512 blocks
    lora_bsr_kernel<<<tiles, 128, SMEM_BYTES>>>(x, w, ids, out);
}

// round 4
// speedup vs baseline: 1.2833x; 1.2833x over previous
#include <cuda_runtime.h>
#include <cstdint>

// Problem constants
#define BB 8
#define SS 2048
#define HH 8192
#define RR 16

// Tiling
#define THREADS 256
#define TILE_S 32              // s-rows per block
#define NWND 4                 // H windows (each warp-pair owns one)
#define HWIN (HH / NWND)       // 2048 h per window
#define CH 64                  // h per window per chunk
#define NC (HWIN / CH)         // 32 chunks
#define XSTR (CH + 4)          // 68 floats: 17 float4 (odd) -> conflict-free LDS.128
#define XFL (NWND * TILE_S * XSTR)   // 8704 floats
#define WFL (NWND * RR * CH)         // 4096 floats
#define BUFFL (XFL + WFL)            // 12800 floats per stage
#define SMEM_BYTES (2 * BUFFL * 4)   // 102400 B -> 2 blocks/SM

__device__ __forceinline__ void fma2(unsigned long long& acc,
                                     unsigned long long a,
                                     unsigned long long b) {
    asm("fma.rn.f32x2 %0, %1, %2, %0;" : "+l"(acc) : "l"(a), "l"(b));
}
__device__ __forceinline__ void cpasync16(uint32_t dst, const float* src) {
    asm volatile("cp.async.cg.shared.global [%0], [%1], 16;" :: "r"(dst), "l"(src));
}
__device__ __forceinline__ void cpcommit() {
    asm volatile("cp.async.commit_group;" ::: "memory");
}
template<int N> __device__ __forceinline__ void cpwait() {
    asm volatile("cp.async.wait_group %0;" :: "n"(N) : "memory");
}

// Stage one chunk (x: 2048 float4, w: 1024 float4) into one smem buffer.
__device__ __forceinline__ void stage(uint32_t sbuf, const float* __restrict__ xb,
                                      const float* __restrict__ wb,
                                      int hoff, int tid) {
#pragma unroll
    for (int i = 0; i < 8; i++) {                  // x: 8 cp.async per thread
        const int idx = tid + i * THREADS;         // 0..2047
        const int v   = idx & 15;                  // float4 within (row,wnd) chunk
        const int row = (idx >> 4) & 31;
        const int wnd = idx >> 9;
        cpasync16(sbuf + (uint32_t)(wnd * (TILE_S * XSTR) + row * XSTR + v * 4) * 4u,
                  xb + (size_t)row * HH + wnd * HWIN + hoff + v * 4);
    }
    const uint32_t swb = sbuf + XFL * 4u;
#pragma unroll
    for (int i = 0; i < 4; i++) {                  // w: 4 cp.async per thread
        const int idx = tid + i * THREADS;         // 0..1023
        const int v   = idx & 15;
        const int r   = (idx >> 4) & 15;
        const int wnd = idx >> 8;
        cpasync16(swb + (uint32_t)(wnd * (RR * CH) + r * CH + v * 4) * 4u,
                  wb + (size_t)r * HH + wnd * HWIN + hoff + v * 4);
    }
    cpcommit();
}

__global__ __launch_bounds__(THREADS, 2)
void lora_bsr_kernel(const float* __restrict__ x,
                     const float* __restrict__ w,
                     const int* __restrict__ ids,
                     float* __restrict__ out)
{
    extern __shared__ float sm[];
    const uint32_t sbase = (uint32_t)__cvta_generic_to_shared(sm);

    const int tile = blockIdx.x;                   // 0..511
    const int b  = tile >> 6;                      // 64 tiles per batch
    const int s0 = (tile & 63) * TILE_S;
    const int aid = ids[b];

    const float* __restrict__ xb = x + (size_t)(b * SS + s0) * HH;
    const float* __restrict__ wb = w + (size_t)aid * RR * HH;

    const int tid  = threadIdx.x;
    const int warp = tid >> 5;
    const int lane = tid & 31;
    const int wnd  = warp >> 1;                    // which H window
    const int rh   = warp & 1;                     // which r-half (8 r's each)

    unsigned long long acc[8];
#pragma unroll
    for (int j = 0; j < 8; j++) acc[j] = 0ULL;

    // prologue: prefetch chunk 0 into buffer 0
    stage(sbase, xb, wb, 0, tid);

    for (int ci = 0; ci < NC; ci++) {
        const float* buf = sm + (ci & 1) * BUFFL;

        if (ci + 1 < NC) {
            stage(sbase + (uint32_t)(((ci + 1) & 1) * BUFFL) * 4u,
                  xb, wb, (ci + 1) * CH, tid);
            cpwait<1>();                           // chunk ci landed
        } else {
            cpwait<0>();
        }
        __syncthreads();

        // compute: lane == s-row; warp -> (H-window, r-half); w reads broadcast
        const float* __restrict__ xrow = buf + wnd * (TILE_S * XSTR) + lane * XSTR;
        const float* __restrict__ wbse = buf + XFL + wnd * (RR * CH) + rh * 8 * CH;
#pragma unroll 2
        for (int hh = 0; hh < CH; hh += 4) {
            const ulonglong2 xv = *(const ulonglong2*)(xrow + hh);
#pragma unroll
            for (int j = 0; j < 8; j++) {
                const ulonglong2 wv = *(const ulonglong2*)(wbse + j * CH + hh);
                fma2(acc[j], xv.x, wv.x);
                fma2(acc[j], xv.y, wv.y);
            }
        }
        __syncthreads();                           // buffer (ci&1) free for reuse
    }

    // cross-window reduction in smem: red[4 wnd][32 rows][17 (16 r + pad)]
    float* red = sm;
#pragma unroll
    for (int j = 0; j < 8; j++) {
        union { unsigned long long u; float2 f; } c; c.u = acc[j];
        red[wnd * (TILE_S * 17) + lane * 17 + rh * 8 + j] = c.f.x + c.f.y;
    }
    __syncthreads();

    float* __restrict__ o = out + (size_t)(b * SS + s0) * RR;
#pragma unroll
    for (int i = 0; i < 2; i++) {
        const int idx = tid + i * THREADS;         // 0..511
        const int row = idx >> 4;
        const int r   = idx & 15;
        float s = 0.f;
#pragma unroll
        for (int wd = 0; wd < NWND; wd++)
            s += red[wd * (TILE_S * 17) + row * 17 + r];
        o[idx] = s;                                // contiguous 512 floats, coalesced
    }
}

extern "C" void kernel_launch(void* const* d_in, const int* in_sizes, int n_in,
                              void* d_out, int out_size) {
    const float* x   = (const float*)d_in[0];   // [B, S, H] f32
    const float* w   = (const float*)d_in[1];   // [MAX_LORAS, R, H] f32
    // d_in[2] = weight_active: dead input (reference overwrites all B slots)
    const int*   ids = (const int*)d_in[3];     // [B] i32
    float* out = (float*)d_out;                 // [B, S, R] f32

    cudaFuncSetAttribute(lora_bsr_kernel,
                         cudaFuncAttributeMaxDynamicSharedMemorySize, SMEM_BYTES);

    const int tiles = BB * (SS / TILE_S);       // 512 blocks
    lora_bsr_kernel<<<tiles, THREADS, SMEM_BYTES>>>(x, w, ids, out);
}

// round 7
// speedup vs baseline: 1.3141x; 1.0240x over previous
#include <cuda_runtime.h>
#include <cstdint>

// Problem constants
#define BB 8
#define SS 2048
#define HH 8192
#define RR 16

// Tiling
#define THREADS 256
#define TILE_S 32              // s-rows per block
#define NWND 4                 // H windows (each warp-pair owns one)
#define HWIN (HH / NWND)       // 2048 h per window
#define CH 32                  // h per window per chunk
#define NC (HWIN / CH)         // 64 chunks
#define XSTR (CH + 4)          // 36 floats: stride%32==4 -> conflict-free LDS.128
#define XFL (NWND * TILE_S * XSTR)   // 4608 floats
#define WFL (NWND * RR * CH)         // 2048 floats
#define BUFFL (XFL + WFL)            // 6656 floats per stage
#define SMEM_BYTES (2 * BUFFL * 4)   // 53248 B -> 3 blocks/SM (reg-capped)

__device__ __forceinline__ void fma2(unsigned long long& acc,
                                     unsigned long long a,
                                     unsigned long long b) {
    asm("fma.rn.f32x2 %0, %1, %2, %0;" : "+l"(acc) : "l"(a), "l"(b));
}
__device__ __forceinline__ void cpasync16(uint32_t dst, const float* src) {
    asm volatile("cp.async.cg.shared.global [%0], [%1], 16;" :: "r"(dst), "l"(src));
}
__device__ __forceinline__ void cpcommit() {
    asm volatile("cp.async.commit_group;" ::: "memory");
}
template<int N> __device__ __forceinline__ void cpwait() {
    asm volatile("cp.async.wait_group %0;" :: "n"(N) : "memory");
}

// Stage one chunk (x: 1024 float4, w: 512 float4) into one smem buffer.
// Per-thread fixed (v,row/r,wnd) decomposition, strided GMEM/SMEM bases
// precomputed by the caller to keep register pressure low.
__device__ __forceinline__ void stage(uint32_t sbuf,
                                      const float* __restrict__ xsrc0,
                                      const float* __restrict__ xsrc1,
                                      const float* __restrict__ wsrc0,
                                      uint32_t xdst0, uint32_t xdst1,
                                      uint32_t wdst0) {
    // x: 4 cp.async per thread; thread owns (wnd,row,v) pairs idx = tid + i*256
    cpasync16(xdst0,                         xsrc0);
    cpasync16(xdst0 + 32 * XSTR * 4u,        xsrc0 + 32 * HH);     // +32 rows? no:
    // NOTE: see caller — xsrc1/xdst1 handle the second pair correctly.
    cpasync16(xdst1,                         xsrc1);
    cpasync16(xdst1 + 32 * XSTR * 4u,        xsrc1 + 32 * HH);
    // w: 2 cp.async per thread
    cpasync16(wdst0,                         wsrc0);
    cpasync16(wdst0 + 8 * CH * 4u,           wsrc0 + 8 * HH);
    cpcommit();
}

__global__ __launch_bounds__(THREADS, 3)
void lora_bsr_kernel(const float* __restrict__ x,
                     const float* __restrict__ w,
                     const int* __restrict__ ids,
                     float* __restrict__ out)
{
    extern __shared__ float sm[];
    const uint32_t sbase = (uint32_t)__cvta_generic_to_shared(sm);

    const int tile = blockIdx.x;                   // 0..511
    const int b  = tile >> 6;                      // 64 tiles per batch
    const int s0 = (tile & 63) * TILE_S;
    const int aid = ids[b];

    const float* __restrict__ xb = x + (size_t)(b * SS + s0) * HH;
    const float* __restrict__ wb = w + (size_t)aid * RR * HH;

    const int tid  = threadIdx.x;
    const int warp = tid >> 5;
    const int lane = tid & 31;
    const int wnd  = warp >> 1;                    // H window
    const int rh   = warp & 1;                     // r-half (8 r's each)

    // ---- precompute staging addresses (constant across chunks except hoff) ----
    // x float4 idx space: 1024 = 4 wnd * 32 row * 8 v ; thread covers idx=tid and idx=tid+256
    // idx -> v = idx&7, row = (idx>>3)&31, wnd_ = idx>>8
    const int xv0 = tid & 7,  xr0 = (tid >> 3) & 31, xw0 = tid >> 8;          // idx = tid   (wnd 0)
    // idx2 = tid + 256 -> same v,row, wnd_ = xw0 + 1... only if tid<256: idx2>>8 = xw0+1. v,row unchanged.
    const float* xsrc0 = xb + (size_t)xr0 * HH + xw0 * HWIN + xv0 * 4;        // wnd xw0
    const float* xsrc1 = xsrc0 + HWIN;                                        // wnd xw0+1 (rows/v same)
    // and each handles +2 windows via the "+32*HH"? NO — fix: second pair is +2 windows:
    // idx3 = tid+512 -> wnd xw0+2 ; idx4 = tid+768 -> wnd xw0+3
    const uint32_t xdst0 = sbase + (uint32_t)((xw0 * TILE_S + xr0) * XSTR + xv0 * 4) * 4u;
    const uint32_t xdst1 = xdst0 + (uint32_t)(TILE_S * XSTR) * 4u;            // wnd+1

    // w float4 idx space: 512 = 4 wnd * 16 r * 8 v ; thread covers idx=tid, tid+256
    const int wv0 = tid & 7,  wr0 = (tid >> 3) & 15, ww0 = tid >> 7;          // idx>>7 in 0..1
    const float* wsrc0 = wb + (size_t)wr0 * HH + ww0 * HWIN + wv0 * 4;
    const uint32_t wdst0 = sbase + (uint32_t)(XFL + (ww0 * RR + wr0) * CH + wv0 * 4) * 4u;

    unsigned long long acc[8];
#pragma unroll
    for (int j = 0; j < 8; j++) acc[j] = 0ULL;

    // prologue: chunk 0 -> buffer 0
    {
        cpasync16(xdst0,                              xsrc0);
        cpasync16(xdst1,                              xsrc0 + HWIN);
        cpasync16(xdst0 + (uint32_t)(2*TILE_S*XSTR)*4u, xsrc0 + 2*HWIN);
        cpasync16(xdst1 + (uint32_t)(2*TILE_S*XSTR)*4u, xsrc0 + 3*HWIN);
        cpasync16(wdst0,                              wsrc0);
        cpasync16(wdst0 + (uint32_t)(2*RR*CH)*4u,     wsrc0 + 2*HWIN);
        cpcommit();
    }

    for (int ci = 0; ci < NC; ci++) {
        const float* buf = sm + (ci & 1) * BUFFL;

        if (ci + 1 < NC) {
            const uint32_t so = (uint32_t)(((ci + 1) & 1) * BUFFL) * 4u;
            const int ho = (ci + 1) * CH;
            cpasync16(xdst0 + so,                              xsrc0 + ho);
            cpasync16(xdst1 + so,                              xsrc0 + HWIN + ho);
            cpasync16(xdst0 + so + (uint32_t)(2*TILE_S*XSTR)*4u, xsrc0 + 2*HWIN + ho);
            cpasync16(xdst1 + so + (uint32_t)(2*TILE_S*XSTR)*4u, xsrc0 + 3*HWIN + ho);
            cpasync16(wdst0 + so,                              wsrc0 + ho);
            cpasync16(wdst0 + so + (uint32_t)(2*RR*CH)*4u,     wsrc0 + 2*HWIN + ho);
            cpcommit();
            cpwait<1>();                           // chunk ci landed
        } else {
            cpwait<0>();
        }
        __syncthreads();

        // compute: lane == s-row; warp -> (H-window, r-half); w reads broadcast
        const float* __restrict__ xrow = buf + wnd * (TILE_S * XSTR) + lane * XSTR;
        const float* __restrict__ wbse = buf + XFL + wnd * (RR * CH) + rh * 8 * CH;
#pragma unroll 2
        for (int hh = 0; hh < CH; hh += 4) {
            const ulonglong2 xv = *(const ulonglong2*)(xrow + hh);
#pragma unroll
            for (int j = 0; j < 8; j++) {
                const ulonglong2 wv = *(const ulonglong2*)(wbse + j * CH + hh);
                fma2(acc[j], xv.x, wv.x);
                fma2(acc[j], xv.y, wv.y);
            }
        }
        __syncthreads();                           // buffer (ci&1) free for reuse
    }

    // cross-window reduction in smem: red[4 wnd][32 rows][17 (16 r + pad)]
    float* red = sm;
#pragma unroll
    for (int j = 0; j < 8; j++) {
        union { unsigned long long u; float2 f; } c; c.u = acc[j];
        red[wnd * (TILE_S * 17) + lane * 17 + rh * 8 + j] = c.f.x + c.f.y;
    }
    __syncthreads();

    float* __restrict__ o = out + (size_t)(b * SS + s0) * RR;
#pragma unroll
    for (int i = 0; i < 2; i++) {
        const int idx = tid + i * THREADS;         // 0..511
        const int row = idx >> 4;
        const int r   = idx & 15;
        float s = 0.f;
#pragma unroll
        for (int wd = 0; wd < NWND; wd++)
            s += red[wd * (TILE_S * 17) + row * 17 + r];
        o[idx] = s;                                // contiguous, coalesced
    }
}

extern "C" void kernel_launch(void* const* d_in, const int* in_sizes, int n_in,
                              void* d_out, int out_size) {
    const float* x   = (const float*)d_in[0];   // [B, S, H] f32
    const float* w   = (const float*)d_in[1];   // [MAX_LORAS, R, H] f32
    // d_in[2] = weight_active: dead input (reference overwrites all B slots)
    const int*   ids = (const int*)d_in[3];     // [B] i32
    float* out = (float*)d_out;                 // [B, S, R] f32

    cudaFuncSetAttribute(lora_bsr_kernel,
                         cudaFuncAttributeMaxDynamicSharedMemorySize, SMEM_BYTES);

    const int tiles = BB * (SS / TILE_S);       // 512 blocks
    lora_bsr_kernel<<<tiles, THREADS, SMEM_BYTES>>>(x, w, ids, out);
}

// round 12
// speedup vs baseline: 1.8378x; 1.3986x over previous
#include <cuda_runtime.h>
#include <cstdint>

// Problem constants
#define BB 8
#define SS 2048
#define HH 8192
#define RR 16

#define THREADS 256               // 8 warps; warp w owns rows [16w, 16w+16)
#define TILE_M 128                // s-rows per block
#define KC 64                     // h per chunk
#define NC (HH / KC)              // 128 chunks
#define XSTR (KC + 4)             // 68: (4g+tig) bank pattern conflict-free
#define XTILE (TILE_M * XSTR)     // 8704 floats per x stage
#define WTILE (RR * XSTR)         // 1088 floats per w stage
#define SMEM_BYTES ((2 * XTILE + 2 * WTILE) * 4)   // 78336 B

__device__ __forceinline__ uint32_t f2tf(float f) {
    uint32_t r; asm("cvt.rna.tf32.f32 %0, %1;" : "=r"(r) : "f"(f)); return r;
}

__global__ __launch_bounds__(THREADS, 1)
void lora_mma_kernel(const float* __restrict__ x,
                     const float* __restrict__ w,
                     const int* __restrict__ ids,
                     float* __restrict__ out)
{
    extern __shared__ float sm[];
    const uint32_t sbase = (uint32_t)__cvta_generic_to_shared(sm);

    const int tid = threadIdx.x, warp = tid >> 5, lane = tid & 31;
    const int g = lane >> 2, tig = lane & 3;       // mma group / thread-in-group

    const int blk = blockIdx.x;                    // 0..127
    const int b = blk >> 4, mt = blk & 15;
    const int aid = ids[b];

    const float* __restrict__ xb = x + ((size_t)(b * SS) + mt * TILE_M) * HH;
    const float* __restrict__ wb = w + (size_t)aid * RR * HH;

    // ---- staging geometry: thread -> (row base xr, float4 col xv) ----
    const int xv = tid & 15, xr = tid >> 4;        // xr 0..15
    const float* __restrict__ xsrc = xb + (size_t)xr * HH + xv * 4;  // rows xr+16i
    const float* __restrict__ wsrc = wb + (size_t)xr * HH + xv * 4;  // w row xr (<16)
    const uint32_t xdst = sbase + (uint32_t)(xr * XSTR + xv * 4) * 4u;
    const uint32_t wdst = sbase + (uint32_t)(2 * XTILE + xr * XSTR + xv * 4) * 4u;

    float4 lx[8]; float4 lw;                       // staged chunk in registers

    float acc[2][4];
#pragma unroll
    for (int nt = 0; nt < 2; nt++)
#pragma unroll
        for (int j = 0; j < 4; j++) acc[nt][j] = 0.f;

    auto ldg = [&](int ci) {
        const float* s = xsrc + ci * KC;
#pragma unroll
        for (int i = 0; i < 8; i++)
            lx[i] = *(const float4*)(s + (size_t)i * 16 * HH);
        lw = *(const float4*)(wsrc + ci * KC);
    };
    auto sts = [&](int st) {
        const uint32_t so = (uint32_t)st * (uint32_t)(XTILE * 4);
#pragma unroll
        for (int i = 0; i < 8; i++) {
            const uint32_t a0 = f2tf(lx[i].x), a1 = f2tf(lx[i].y);
            const uint32_t a2 = f2tf(lx[i].z), a3 = f2tf(lx[i].w);
            asm volatile("st.shared.v4.b32 [%0], {%1,%2,%3,%4};"
                :: "r"(xdst + so + (uint32_t)(i * 16 * XSTR * 4)),
                   "r"(a0), "r"(a1), "r"(a2), "r"(a3));
        }
        const uint32_t b0 = f2tf(lw.x), b1 = f2tf(lw.y);
        const uint32_t b2 = f2tf(lw.z), b3 = f2tf(lw.w);
        asm volatile("st.shared.v4.b32 [%0], {%1,%2,%3,%4};"
            :: "r"(wdst + (uint32_t)st * (uint32_t)(WTILE * 4)),
               "r"(b0), "r"(b1), "r"(b2), "r"(b3));
    };

    // prologue: chunk 0 -> buffer 0
    ldg(0); sts(0);
    __syncthreads();

    for (int ci = 0; ci < NC; ci++) {
        if (ci + 1 < NC) ldg(ci + 1);              // LDGs in flight over compute

        // ---- compute chunk ci from buffer ci&1 ----
        {
            const int st = ci & 1;
            const float* xt = sm + st * XTILE + (warp * 16) * XSTR;
            const float* wt = sm + 2 * XTILE + st * WTILE;
            const float* xr0 = xt + g * XSTR + tig;         // A rows g / g+8
            const float* xr1 = xt + (g + 8) * XSTR + tig;
            const float* wr0 = wt + g * XSTR + tig;         // B n-tile 0 (n = g)
            const float* wr1 = wt + (8 + g) * XSTR + tig;   // B n-tile 1 (n = 8+g)
#pragma unroll
            for (int ks = 0; ks < KC / 8; ks++) {
                const int k0 = ks * 8;
                const uint32_t a0 = __float_as_uint(xr0[k0]);
                const uint32_t a1 = __float_as_uint(xr1[k0]);
                const uint32_t a2 = __float_as_uint(xr0[k0 + 4]);
                const uint32_t a3 = __float_as_uint(xr1[k0 + 4]);
                const uint32_t b00 = __float_as_uint(wr0[k0]);
                const uint32_t b01 = __float_as_uint(wr0[k0 + 4]);
                const uint32_t b10 = __float_as_uint(wr1[k0]);
                const uint32_t b11 = __float_as_uint(wr1[k0 + 4]);
                asm volatile(
                    "mma.sync.aligned.m16n8k8.row.col.f32.tf32.tf32.f32 "
                    "{%0,%1,%2,%3}, {%4,%5,%6,%7}, {%8,%9}, {%0,%1,%2,%3};"
                    : "+f"(acc[0][0]), "+f"(acc[0][1]),
                      "+f"(acc[0][2]), "+f"(acc[0][3])
                    : "r"(a0), "r"(a1), "r"(a2), "r"(a3), "r"(b00), "r"(b01));
                asm volatile(
                    "mma.sync.aligned.m16n8k8.row.col.f32.tf32.tf32.f32 "
                    "{%0,%1,%2,%3}, {%4,%5,%6,%7}, {%8,%9}, {%0,%1,%2,%3};"
                    : "+f"(acc[1][0]), "+f"(acc[1][1]),
                      "+f"(acc[1][2]), "+f"(acc[1][3])
                    : "r"(a0), "r"(a1), "r"(a2), "r"(a3), "r"(b10), "r"(b11));
            }
        }

        if (ci + 1 < NC) sts((ci + 1) & 1);        // fill other buffer
        __syncthreads();                           // publish STS + retire reads
    }

    // ---- epilogue: C fragment -> gmem (c0,c1 row g; c2,c3 row g+8) ----
    const int row0 = mt * TILE_M + warp * 16 + g;
    float* __restrict__ o = out + ((size_t)(b * SS) + row0) * RR;
#pragma unroll
    for (int nt = 0; nt < 2; nt++) {
        *(float2*)(o + nt * 8 + 2 * tig) =
            make_float2(acc[nt][0], acc[nt][1]);
        *(float2*)(o + (size_t)8 * RR + nt * 8 + 2 * tig) =
            make_float2(acc[nt][2], acc[nt][3]);
    }
}

extern "C" void kernel_launch(void* const* d_in, const int* in_sizes, int n_in,
                              void* d_out, int out_size) {
    const float* x   = (const float*)d_in[0];   // [B, S, H] f32
    const float* w   = (const float*)d_in[1];   // [MAX_LORAS, R, H] f32
    // d_in[2] = weight_active: dead input (reference overwrites all B slots)
    const int*   ids = (const int*)d_in[3];     // [B] i32
    float* out = (float*)d_out;                 // [B, S, R] f32

    cudaFuncSetAttribute(lora_mma_kernel,
                         cudaFuncAttributeMaxDynamicSharedMemorySize, SMEM_BYTES);

    lora_mma_kernel<<<BB * (SS / TILE_M), THREADS, SMEM_BYTES>>>(x, w, ids, out);
}

// round 15
// speedup vs baseline: 1.9518x; 1.0620x over previous
#include <cuda_runtime.h>
#include <cstdint>

// Problem constants
#define BB 8
#define SS 2048
#define HH 8192
#define RR 16

#define THREADS 256               // 8 warps = 4 m-tiles x 2 n-tiles
#define TILE_M 64                 // s-rows per block
#define KC 64                     // h per chunk
#define NC (HH / KC)              // 128 chunks
#define XSTR (KC + 4)             // 68: (4g+tig+k) bank pattern conflict-free
#define XTILE (TILE_M * XSTR)     // 4352 floats per x stage
#define WTILE (RR * XSTR)         // 1088 floats per w stage
#define SMEM_BYTES ((2 * XTILE + 2 * WTILE) * 4)   // 43520 B -> 2 blocks/SM

__device__ __forceinline__ uint32_t f2tf(float f) {
    uint32_t r; asm("cvt.rna.tf32.f32 %0, %1;" : "=r"(r) : "f"(f)); return r;
}

__global__ __launch_bounds__(THREADS, 2)
void lora_mma_kernel(const float* __restrict__ x,
                     const float* __restrict__ w,
                     const int* __restrict__ ids,
                     float* __restrict__ out)
{
    extern __shared__ float sm[];
    const uint32_t sbase = (uint32_t)__cvta_generic_to_shared(sm);

    const int tid = threadIdx.x, warp = tid >> 5, lane = tid & 31;
    const int g = lane >> 2, tig = lane & 3;       // mma group / thread-in-group
    const int mtile = warp >> 1, nt = warp & 1;    // warp -> (m16 tile, n8 tile)

    const int blk = blockIdx.x;                    // 0..255
    const int b = blk >> 5, mt = blk & 31;         // 32 m-tiles per batch
    const int aid = ids[b];

    const float* __restrict__ xb = x + ((size_t)(b * SS) + mt * TILE_M) * HH;
    const float* __restrict__ wb = w + (size_t)aid * RR * HH;

    // ---- staging geometry: thread -> (row base xr, float4 col xv) ----
    const int xv = tid & 15, xr = tid >> 4;        // xr 0..15
    const float* __restrict__ xsrc = xb + (size_t)xr * HH + xv * 4;  // rows xr+16i
    const float* __restrict__ wsrc = wb + (size_t)xr * HH + xv * 4;  // w row xr
    const uint32_t xdst = sbase + (uint32_t)(xr * XSTR + xv * 4) * 4u;
    const uint32_t wdst = sbase + (uint32_t)(2 * XTILE + xr * XSTR + xv * 4) * 4u;

    float4 lx[4]; float4 lw;                       // staged chunk in registers

    float acc[4];
#pragma unroll
    for (int j = 0; j < 4; j++) acc[j] = 0.f;

    auto ldg = [&](int ci) {
        const float* s = xsrc + ci * KC;
#pragma unroll
        for (int i = 0; i < 4; i++)
            lx[i] = *(const float4*)(s + (size_t)i * 16 * HH);
        lw = *(const float4*)(wsrc + ci * KC);
    };
    auto sts = [&](int st) {
        const uint32_t so = (uint32_t)st * (uint32_t)(XTILE * 4);
#pragma unroll
        for (int i = 0; i < 4; i++) {
            const uint32_t a0 = f2tf(lx[i].x), a1 = f2tf(lx[i].y);
            const uint32_t a2 = f2tf(lx[i].z), a3 = f2tf(lx[i].w);
            asm volatile("st.shared.v4.b32 [%0], {%1,%2,%3,%4};"
                :: "r"(xdst + so + (uint32_t)(i * 16 * XSTR * 4)),
                   "r"(a0), "r"(a1), "r"(a2), "r"(a3));
        }
        const uint32_t b0 = f2tf(lw.x), b1 = f2tf(lw.y);
        const uint32_t b2 = f2tf(lw.z), b3 = f2tf(lw.w);
        asm volatile("st.shared.v4.b32 [%0], {%1,%2,%3,%4};"
            :: "r"(wdst + (uint32_t)st * (uint32_t)(WTILE * 4)),
               "r"(b0), "r"(b1), "r"(b2), "r"(b3));
    };

    // prologue: chunk 0 -> buffer 0
    ldg(0); sts(0);
    __syncthreads();

    for (int ci = 0; ci < NC; ci++) {
        if (ci + 1 < NC) ldg(ci + 1);              // LDGs in flight over compute

        // ---- compute chunk ci from buffer ci&1 ----
        {
            const int st = ci & 1;
            const float* xt = sm + st * XTILE + mtile * 16 * XSTR;
            const float* wt = sm + 2 * XTILE + st * WTILE + nt * 8 * XSTR;
            const float* xr0 = xt + g * XSTR + tig;         // A rows g / g+8
            const float* xr1 = xt + (g + 8) * XSTR + tig;
            const float* wr  = wt + g * XSTR + tig;         // B n-tile nt
#pragma unroll
            for (int ks = 0; ks < KC / 8; ks++) {
                const int k0 = ks * 8;
                const uint32_t a0 = __float_as_uint(xr0[k0]);
                const uint32_t a1 = __float_as_uint(xr1[k0]);
                const uint32_t a2 = __float_as_uint(xr0[k0 + 4]);
                const uint32_t a3 = __float_as_uint(xr1[k0 + 4]);
                const uint32_t b0 = __float_as_uint(wr[k0]);
                const uint32_t b1 = __float_as_uint(wr[k0 + 4]);
                asm volatile(
                    "mma.sync.aligned.m16n8k8.row.col.f32.tf32.tf32.f32 "
                    "{%0,%1,%2,%3}, {%4,%5,%6,%7}, {%8,%9}, {%0,%1,%2,%3};"
                    : "+f"(acc[0]), "+f"(acc[1]), "+f"(acc[2]), "+f"(acc[3])
                    : "r"(a0), "r"(a1), "r"(a2), "r"(a3), "r"(b0), "r"(b1));
            }
        }

        if (ci + 1 < NC) sts((ci + 1) & 1);        // fill other buffer
        __syncthreads();                           // publish STS + retire reads
    }

    // ---- epilogue: C fragment -> gmem (c0,c1 row g; c2,c3 row g+8) ----
    const int row0 = mt * TILE_M + mtile * 16 + g;
    float* __restrict__ o = out + ((size_t)(b * SS) + row0) * RR + nt * 8;
    *(float2*)(o + 2 * tig) = make_float2(acc[0], acc[1]);
    *(float2*)(o + (size_t)8 * RR + 2 * tig) = make_float2(acc[2], acc[3]);
}

extern "C" void kernel_launch(void* const* d_in, const int* in_sizes, int n_in,
                              void* d_out, int out_size) {
    const float* x   = (const float*)d_in[0];   // [B, S, H] f32
    const float* w   = (const float*)d_in[1];   // [MAX_LORAS, R, H] f32
    // d_in[2] = weight_active: dead input (reference overwrites all B slots)
    const int*   ids = (const int*)d_in[3];     // [B] i32
    float* out = (float*)d_out;                 // [B, S, R] f32

    cudaFuncSetAttribute(lora_mma_kernel,
                         cudaFuncAttributeMaxDynamicSharedMemorySize, SMEM_BYTES);

    lora_mma_kernel<<<BB * (SS / TILE_M), THREADS, SMEM_BYTES>>>(x, w, ids, out);
}

// round 17
// speedup vs baseline: 2.2863x; 1.1714x over previous
#include <cuda_runtime.h>
#include <cstdint>

// Problem constants
#define BB 8
#define SS 2048
#define HH 8192
#define RR 16

#define THREADS 256               // 8 warps = 4 m-tiles x 2 n-tiles
#define TILE_M 64                 // s-rows per block
#define KC 64                     // h per chunk
#define NC (HH / KC)              // 128 chunks
#define XSTR (KC + 4)             // 68: (4g+tig+k) bank pattern conflict-free
#define XTILE (TILE_M * XSTR)     // 4352 floats per x stage
#define WTILE (RR * XSTR)         // 1088 floats per w stage
#define SMEM_BYTES ((2 * XTILE + 2 * WTILE) * 4)   // 43520 B -> 2 blocks/SM

__device__ __forceinline__ uint32_t f2tf(float f) {
    uint32_t r; asm("cvt.rna.tf32.f32 %0, %1;" : "=r"(r) : "f"(f)); return r;
}

__global__ __launch_bounds__(THREADS, 2)
void lora_mma_kernel(const float* __restrict__ x,
                     const float* __restrict__ w,
                     const int* __restrict__ ids,
                     float* __restrict__ out)
{
    extern __shared__ float sm[];
    const uint32_t sbase = (uint32_t)__cvta_generic_to_shared(sm);

    const int tid = threadIdx.x, warp = tid >> 5, lane = tid & 31;
    const int g = lane >> 2, tig = lane & 3;       // mma group / thread-in-group
    const int mtile = warp >> 1, nt = warp & 1;    // warp -> (m16 tile, n8 tile)

    const int blk = blockIdx.x;                    // 0..255
    const int b = blk >> 5, mt = blk & 31;         // 32 m-tiles per batch
    const int aid = ids[b];

    const float* __restrict__ xb = x + ((size_t)(b * SS) + mt * TILE_M) * HH;
    const float* __restrict__ wb = w + (size_t)aid * RR * HH;

    // ---- staging geometry: thread -> (row base xr, float4 col xv) ----
    const int xv = tid & 15, xr = tid >> 4;        // xr 0..15
    const float* __restrict__ xsrc = xb + (size_t)xr * HH + xv * 4;  // rows xr+16i
    const float* __restrict__ wsrc = wb + (size_t)xr * HH + xv * 4;  // w row xr
    const uint32_t xdst = sbase + (uint32_t)(xr * XSTR + xv * 4) * 4u;
    const uint32_t wdst = sbase + (uint32_t)(2 * XTILE + xr * XSTR + xv * 4) * 4u;

    // Two register stage-sets: prefetch distance 2 (full chunk-iter of cover)
    float4 lxA[4], lxB[4]; float4 lwA, lwB;

    float acc[4];
#pragma unroll
    for (int j = 0; j < 4; j++) acc[j] = 0.f;

    auto ldg = [&](int ci, float4 (&lx)[4], float4& lw) {
        const float* s = xsrc + ci * KC;
#pragma unroll
        for (int i = 0; i < 4; i++)
            lx[i] = *(const float4*)(s + (size_t)i * 16 * HH);
        lw = *(const float4*)(wsrc + ci * KC);
    };
    auto sts = [&](int st, const float4 (&lx)[4], const float4& lw) {
        const uint32_t so = (uint32_t)st * (uint32_t)(XTILE * 4);
#pragma unroll
        for (int i = 0; i < 4; i++) {
            const uint32_t a0 = f2tf(lx[i].x), a1 = f2tf(lx[i].y);
            const uint32_t a2 = f2tf(lx[i].z), a3 = f2tf(lx[i].w);
            asm volatile("st.shared.v4.b32 [%0], {%1,%2,%3,%4};"
                :: "r"(xdst + so + (uint32_t)(i * 16 * XSTR * 4)),
                   "r"(a0), "r"(a1), "r"(a2), "r"(a3));
        }
        const uint32_t b0 = f2tf(lw.x), b1 = f2tf(lw.y);
        const uint32_t b2 = f2tf(lw.z), b3 = f2tf(lw.w);
        asm volatile("st.shared.v4.b32 [%0], {%1,%2,%3,%4};"
            :: "r"(wdst + (uint32_t)st * (uint32_t)(WTILE * 4)),
               "r"(b0), "r"(b1), "r"(b2), "r"(b3));
    };
    auto compute = [&](int st) {
        const float* xt = sm + st * XTILE + mtile * 16 * XSTR;
        const float* wt = sm + 2 * XTILE + st * WTILE + nt * 8 * XSTR;
        const float* xr0 = xt + g * XSTR + tig;            // A rows g / g+8
        const float* xr1 = xt + (g + 8) * XSTR + tig;
        const float* wr  = wt + g * XSTR + tig;            // B n-tile nt
#pragma unroll
        for (int ks = 0; ks < KC / 8; ks++) {
            const int k0 = ks * 8;
            const uint32_t a0 = __float_as_uint(xr0[k0]);
            const uint32_t a1 = __float_as_uint(xr1[k0]);
            const uint32_t a2 = __float_as_uint(xr0[k0 + 4]);
            const uint32_t a3 = __float_as_uint(xr1[k0 + 4]);
            const uint32_t b0 = __float_as_uint(wr[k0]);
            const uint32_t b1 = __float_as_uint(wr[k0 + 4]);
            asm volatile(
                "mma.sync.aligned.m16n8k8.row.col.f32.tf32.tf32.f32 "
                "{%0,%1,%2,%3}, {%4,%5,%6,%7}, {%8,%9}, {%0,%1,%2,%3};"
                : "+f"(acc[0]), "+f"(acc[1]), "+f"(acc[2]), "+f"(acc[3])
                : "r"(a0), "r"(a1), "r"(a2), "r"(a3), "r"(b0), "r"(b1));
        }
    };

    // prologue: chunks 0,1 in flight; chunk 0 staged to buf0
    ldg(0, lxA, lwA);
    ldg(1, lxB, lwB);
    sts(0, lxA, lwA);
    __syncthreads();

    for (int ci = 0; ci < NC; ci += 2) {
        // half-iter 1: A-regs were consumed by sts last iter -> refill 2 ahead
        if (ci + 2 < NC) ldg(ci + 2, lxA, lwA);    // issued 1 full iter ahead
        compute(0);                                // chunk ci from buf0
        sts(1, lxB, lwB);                          // chunk ci+1 -> buf1 (B loaded 1 iter ago)
        __syncthreads();                           // publish buf1; buf0 free

        // half-iter 2
        if (ci + 3 < NC) ldg(ci + 3, lxB, lwB);
        compute(1);                                // chunk ci+1 from buf1
        if (ci + 2 < NC) sts(0, lxA, lwA);         // chunk ci+2 -> buf0
        __syncthreads();                           // publish buf0; buf1 free
    }

    // ---- epilogue: C fragment -> gmem (c0,c1 row g; c2,c3 row g+8) ----
    const int row0 = mt * TILE_M + mtile * 16 + g;
    float* __restrict__ o = out + ((size_t)(b * SS) + row0) * RR + nt * 8;
    *(float2*)(o + 2 * tig) = make_float2(acc[0], acc[1]);
    *(float2*)(o + (size_t)8 * RR + 2 * tig) = make_float2(acc[2], acc[3]);
}

extern "C" void kernel_launch(void* const* d_in, const int* in_sizes, int n_in,
                              void* d_out, int out_size) {
    const float* x   = (const float*)d_in[0];   // [B, S, H] f32
    const float* w   = (const float*)d_in[1];   // [MAX_LORAS, R, H] f32
    // d_in[2] = weight_active: dead input (reference overwrites all B slots)
    const int*   ids = (const int*)d_in[3];     // [B] i32
    float* out = (float*)d_out;                 // [B, S, R] f32

    cudaFuncSetAttribute(lora_mma_kernel,
                         cudaFuncAttributeMaxDynamicSharedMemorySize, SMEM_BYTES);

    lora_mma_kernel<<<BB * (SS / TILE_M), THREADS, SMEM_BYTES>>>(x, w, ids, out);
}